// round 6
// baseline (speedup 1.0000x reference)
#include <cuda_runtime.h>
#include <cuda_fp16.h>

#define NN      100000
#define EEDGES  1600000
#define KIN     128
#define HF      128      // HEADS * OUT_F
#define NHEADS  4

typedef unsigned long long u64;

// ---------------- scratch (static device globals; no allocations) ----------------
__device__ __align__(16) __half g_hh[(size_t)NN * HF];      // 25.6 MB  h = xW (fp16)
__device__ __align__(16) float g_asrc[NN * NHEADS];
__device__ __align__(16) float g_adst[NN * NHEADS];
__device__ int g_cnt[NN];          // per-dst in-degree (excl self loop)
__device__ int g_off[NN];          // bucket start per dst
__device__ int g_cur[NN];          // scatter cursors
__device__ int g_ss[EEDGES];       // src index of each edge, bucketed by dst
__device__ int g_total;            // global bucket cursor

// ---------------- f32x2 packed-FMA helpers ----------------
__device__ __forceinline__ u64 pack2(float lo, float hi) {
    u64 r; asm("mov.b64 %0, {%1, %2};" : "=l"(r) : "f"(lo), "f"(hi)); return r;
}
__device__ __forceinline__ void ffma2(u64& d, u64 a, u64 b) {
    asm("fma.rn.f32x2 %0, %1, %2, %0;" : "+l"(d) : "l"(a), "l"(b));
}
__device__ __forceinline__ void unpack2(u64 v, float& lo, float& hi) {
    asm("mov.b64 {%0, %1}, %2;" : "=f"(lo), "=f"(hi) : "l"(v));
}

// ---------------- 1. zero per-dst counters + cursor ----------------
__global__ void zero_cnt_kernel(int n) {
    int i = blockIdx.x * blockDim.x + threadIdx.x;
    if (i < n) g_cnt[i] = 0;
    if (i == 0) g_total = 0;
}

// ---------------- 2. GEMM + fused attention-logit epilogue ----------------
// h = x @ W (f32x2 packed FFMA). a_src/a_dst from fp32 register accumulators
// (8-lane shfl reduction); h stored fp16 for the bandwidth-bound gather pass.
__global__ __launch_bounds__(256) void gemm_kernel(const float* __restrict__ x,
                                                   const float* __restrict__ W,
                                                   const float* __restrict__ att_src,
                                                   const float* __restrict__ att_dst,
                                                   int n) {
    __shared__ __align__(16) float xs[32][136];
    __shared__ __align__(16) float ws[32][132];
    __shared__ float satt[2][HF];                 // [0]=att_src, [1]=att_dst
    int tid = threadIdx.x;
    int ty = tid >> 4, tx = tid & 15;
    int brow = blockIdx.x * 128;

    if (tid < 128) satt[0][tid] = att_src[tid];
    else           satt[1][tid - 128] = att_dst[tid - 128];

    u64 acc2[2][4][2][2];            // [ri][i][ci][j2]
    #pragma unroll
    for (int a = 0; a < 2; a++)
        #pragma unroll
        for (int b = 0; b < 4; b++)
            #pragma unroll
            for (int c = 0; c < 2; c++)
                #pragma unroll
                for (int d = 0; d < 2; d++) acc2[a][b][c][d] = 0ull;

    for (int kc = 0; kc < 4; kc++) {
        int k0 = kc * 32;
        #pragma unroll
        for (int it = 0; it < 4; it++) {          // x tile (transposed store)
            int f = tid + it * 256;
            int r = f >> 3, kq = f & 7;
            float4 v = make_float4(0.f, 0.f, 0.f, 0.f);
            if (brow + r < n)
                v = *(const float4*)(x + (size_t)(brow + r) * KIN + k0 + kq * 4);
            xs[kq * 4 + 0][r] = v.x; xs[kq * 4 + 1][r] = v.y;
            xs[kq * 4 + 2][r] = v.z; xs[kq * 4 + 3][r] = v.w;
        }
        #pragma unroll
        for (int it = 0; it < 4; it++) {          // W tile
            int f = tid + it * 256;
            int k = f >> 5, c4 = f & 31;
            *(float4*)&ws[k][c4 * 4] =
                *(const float4*)(W + (size_t)(k0 + k) * HF + c4 * 4);
        }
        __syncthreads();

        #pragma unroll
        for (int k = 0; k < 32; k++) {
            float4 a0 = *(float4*)&xs[k][ty * 4];
            float4 a1 = *(float4*)&xs[k][64 + ty * 4];
            float4 b0 = *(float4*)&ws[k][tx * 4];
            float4 b1 = *(float4*)&ws[k][64 + tx * 4];
            u64 bp[2][2] = {{pack2(b0.x, b0.y), pack2(b0.z, b0.w)},
                            {pack2(b1.x, b1.y), pack2(b1.z, b1.w)}};
            float av[2][4] = {{a0.x, a0.y, a0.z, a0.w}, {a1.x, a1.y, a1.z, a1.w}};
            #pragma unroll
            for (int ri = 0; ri < 2; ri++)
                #pragma unroll
                for (int i = 0; i < 4; i++) {
                    u64 ad = pack2(av[ri][i], av[ri][i]);
                    #pragma unroll
                    for (int ci = 0; ci < 2; ci++) {
                        ffma2(acc2[ri][i][ci][0], ad, bp[ci][0]);
                        ffma2(acc2[ri][i][ci][1], ad, bp[ci][1]);
                    }
                }
        }
        __syncthreads();
    }

    // epilogue: store fp16 h rows + fused fp32 a_src/a_dst
    #pragma unroll
    for (int ri = 0; ri < 2; ri++)
        #pragma unroll
        for (int i = 0; i < 4; i++) {
            int r = brow + ri * 64 + ty * 4 + i;
            float o[2][4];
            #pragma unroll
            for (int ci = 0; ci < 2; ci++) {
                unpack2(acc2[ri][i][ci][0], o[ci][0], o[ci][1]);
                unpack2(acc2[ri][i][ci][1], o[ci][2], o[ci][3]);
            }
            if (r < n) {
                #pragma unroll
                for (int ci = 0; ci < 2; ci++) {
                    __half2 h01 = __floats2half2_rn(o[ci][0], o[ci][1]);
                    __half2 h23 = __floats2half2_rn(o[ci][2], o[ci][3]);
                    uint2 u = make_uint2(*(unsigned*)&h01, *(unsigned*)&h23);
                    *(uint2*)(g_hh + (size_t)r * HF + ci * 64 + tx * 4) = u;
                }
            }
            // per-(row, head) partial dots; head(ci) = ci*2 + (tx>>3)
            float ps[2], pd[2];
            #pragma unroll
            for (int ci = 0; ci < 2; ci++) {
                const float* va = &satt[0][ci * 64 + tx * 4];
                const float* vd = &satt[1][ci * 64 + tx * 4];
                ps[ci] = o[ci][0]*va[0] + o[ci][1]*va[1] + o[ci][2]*va[2] + o[ci][3]*va[3];
                pd[ci] = o[ci][0]*vd[0] + o[ci][1]*vd[1] + o[ci][2]*vd[2] + o[ci][3]*vd[3];
            }
            #pragma unroll
            for (int off = 1; off < 8; off <<= 1) {
                #pragma unroll
                for (int ci = 0; ci < 2; ci++) {
                    ps[ci] += __shfl_xor_sync(0xffffffffu, ps[ci], off);
                    pd[ci] += __shfl_xor_sync(0xffffffffu, pd[ci], off);
                }
            }
            if ((tx & 7) == 0 && r < n) {
                int hd = tx >> 3;                  // 0 or 1
                g_asrc[r * 4 + hd]     = ps[0];
                g_asrc[r * 4 + 2 + hd] = ps[1];
                g_adst[r * 4 + hd]     = pd[0];
                g_adst[r * 4 + 2 + hd] = pd[1];
            }
        }
}

// ---------------- 3. histogram of destinations ----------------
__global__ void hist_kernel(const int* __restrict__ ei, int E) {
    int i = blockIdx.x * blockDim.x + threadIdx.x;
    if (i < E) atomicAdd(&g_cnt[ei[E + i]], 1);
}

// ---------------- 4. bucket offsets: block scan + global atomic base ----------------
__global__ __launch_bounds__(1024) void offsets_kernel(int n) {
    __shared__ int wsum[32];
    __shared__ int sbase;
    int tid = threadIdx.x, lane = tid & 31, wid = tid >> 5;
    int i = blockIdx.x * 1024 + tid;
    int v = (i < n) ? g_cnt[i] : 0;
    int incl = v;
    #pragma unroll
    for (int o = 1; o < 32; o <<= 1) {
        int t = __shfl_up_sync(0xffffffffu, incl, o);
        if (lane >= o) incl += t;
    }
    if (lane == 31) wsum[wid] = incl;
    __syncthreads();
    if (wid == 0) {
        int wv = wsum[lane];
        int wincl = wv;
        #pragma unroll
        for (int o = 1; o < 32; o <<= 1) {
            int t = __shfl_up_sync(0xffffffffu, wincl, o);
            if (lane >= o) wincl += t;
        }
        wsum[lane] = wincl - wv;
        if (lane == 31) sbase = atomicAdd(&g_total, wincl);
    }
    __syncthreads();
    int excl = incl - v + wsum[wid] + sbase;
    if (i < n) { g_off[i] = excl; g_cur[i] = excl; }
}

// ---------------- 5. bucket src indices by destination ----------------
__global__ void scatter_kernel(const int* __restrict__ ei, int E) {
    int i = blockIdx.x * blockDim.x + threadIdx.x;
    if (i >= E) return;
    int d = ei[E + i];
    int p = atomicAdd(&g_cur[d], 1);
    g_ss[p] = ei[i];
}

// ---------------- 6. single-pass gather/softmax/accumulate (warp per node) ----------------
__global__ __launch_bounds__(256) void agg_kernel(const float* __restrict__ bias,
                                                  float* __restrict__ out, int n) {
    int w = (blockIdx.x * blockDim.x + threadIdx.x) >> 5;
    int lane = threadIdx.x & 31;
    if (w >= n) return;
    int d = w;
    int hd = lane >> 3;
    float adst = g_adst[d * 4 + hd];
    int beg = g_off[d], cnt = g_cnt[d];

    // self loop
    float e0 = g_asrc[d * 4 + hd] + adst;
    e0 = e0 > 0.f ? e0 : 0.2f * e0;
    float ex0 = __expf(e0);
    float ssum = ex0;
    float4 acc;
    {
        uint2 u = *((const uint2*)(g_hh + (size_t)d * HF) + lane);
        float2 f01 = __half22float2(*(__half2*)&u.x);
        float2 f23 = __half22float2(*(__half2*)&u.y);
        acc = make_float4(f01.x * ex0, f01.y * ex0, f23.x * ex0, f23.y * ex0);
    }

    for (int c0 = 0; c0 < cnt; c0 += 32) {
        int j = c0 + lane;
        int spre = (j < cnt) ? g_ss[beg + j] : 0;
        int m = cnt - c0; if (m > 32) m = 32;
        #pragma unroll 8
        for (int t = 0; t < m; t++) {
            int s = __shfl_sync(0xffffffffu, spre, t);
            float e = g_asrc[s * 4 + hd] + adst;
            e = e > 0.f ? e : 0.2f * e;
            float ex = __expf(e);
            ssum += ex;
            uint2 u = *((const uint2*)(g_hh + (size_t)s * HF) + lane);
            float2 f01 = __half22float2(*(__half2*)&u.x);
            float2 f23 = __half22float2(*(__half2*)&u.y);
            acc.x += f01.x * ex; acc.y += f01.y * ex;
            acc.z += f23.x * ex; acc.w += f23.y * ex;
        }
    }

    float inv = 1.0f / (ssum + 1e-16f);
    float4 b = *(const float4*)(bias + lane * 4);
    float4 o = make_float4(acc.x * inv + b.x, acc.y * inv + b.y,
                           acc.z * inv + b.z, acc.w * inv + b.w);
    *(float4*)(out + (size_t)d * HF + lane * 4) = o;
}

// ---------------- launch: fork edge-prep onto a side stream ----------------
extern "C" void kernel_launch(void* const* d_in, const int* in_sizes, int n_in,
                              void* d_out, int out_size) {
    const float* x       = (const float*)d_in[0];
    const int*   ei      = (const int*)d_in[1];     // int32 (jax default x64-disabled)
    const float* W       = (const float*)d_in[2];
    const float* att_src = (const float*)d_in[3];
    const float* att_dst = (const float*)d_in[4];
    const float* bias    = (const float*)d_in[5];
    float* out = (float*)d_out;

    int n = in_sizes[0] / KIN;     // 100000
    int E = in_sizes[1] / 2;       // 1600000

    static cudaStream_t s2 = nullptr;
    static cudaEvent_t evFork = nullptr, evJoin = nullptr;
    if (s2 == nullptr) {
        cudaStreamCreateWithFlags(&s2, cudaStreamNonBlocking);
        cudaEventCreateWithFlags(&evFork, cudaEventDisableTiming);
        cudaEventCreateWithFlags(&evJoin, cudaEventDisableTiming);
    }

    // fork: edge-prep chain on s2, GEMM chain on the launch stream
    cudaEventRecord(evFork, 0);
    cudaStreamWaitEvent(s2, evFork, 0);

    zero_cnt_kernel<<<(n + 1023) / 1024, 1024, 0, s2>>>(n);
    hist_kernel<<<(E + 255) / 256, 256, 0, s2>>>(ei, E);
    offsets_kernel<<<(n + 1023) / 1024, 1024, 0, s2>>>(n);
    scatter_kernel<<<(E + 255) / 256, 256, 0, s2>>>(ei, E);
    cudaEventRecord(evJoin, s2);

    gemm_kernel<<<(n + 127) / 128, 256>>>(x, W, att_src, att_dst, n);

    // join, then aggregate
    cudaStreamWaitEvent(0, evJoin, 0);
    {
        long long threads = (long long)n * 32;
        int blocks = (int)((threads + 255) / 256);
        agg_kernel<<<blocks, 256>>>(bias, out, n);
    }
}

// round 7
// speedup vs baseline: 1.2978x; 1.2978x over previous
#include <cuda_runtime.h>
#include <cuda_fp16.h>

#define NN      100000
#define EEDGES  1600000
#define KIN     128
#define HF      128      // HEADS * OUT_F
#define NHEADS  4

typedef unsigned long long u64;

// ---------------- scratch (static device globals; no allocations) ----------------
__device__ __align__(16) float  g_h[(size_t)NN * HF];       // 51.2 MB  h = xW (fp32)
__device__ __align__(16) __half g_hh[(size_t)NN * HF];      // 25.6 MB  h (fp16 mirror)
__device__ __align__(16) float g_asrc[NN * NHEADS];
__device__ __align__(16) float g_adst[NN * NHEADS];
__device__ int g_cnt[NN];          // per-dst in-degree (excl self loop)
__device__ int g_off[NN];          // bucket start per dst
__device__ int g_cur[NN];          // scatter cursors
__device__ int g_ss[EEDGES];       // src index of each edge, bucketed by dst
__device__ int g_total;            // global bucket cursor

// ---------------- f32x2 packed-FMA helpers ----------------
__device__ __forceinline__ u64 pack2(float lo, float hi) {
    u64 r; asm("mov.b64 %0, {%1, %2};" : "=l"(r) : "f"(lo), "f"(hi)); return r;
}
__device__ __forceinline__ void ffma2(u64& d, u64 a, u64 b) {
    asm("fma.rn.f32x2 %0, %1, %2, %0;" : "+l"(d) : "l"(a), "l"(b));
}
__device__ __forceinline__ void unpack2(u64 v, float& lo, float& hi) {
    asm("mov.b64 {%0, %1}, %2;" : "=f"(lo), "=f"(hi) : "l"(v));
}

// fp16x2 -> 2x fp32 via integer ALU only (no F2F pipe).
// Exact for normals; fp16 subnormals land within 1.2e-4 absolute (negligible here).
__device__ __forceinline__ float2 h2f2_alu(unsigned u) {
    unsigned lo_s = (u << 16) & 0x80000000u;
    unsigned lo_m = (u & 0x7fffu) + 0x1C000u;
    unsigned hi_s = u & 0x80000000u;
    unsigned hi_m = ((u >> 16) & 0x7fffu) + 0x1C000u;
    return make_float2(__uint_as_float(lo_s | (lo_m << 13)),
                       __uint_as_float(hi_s | (hi_m << 13)));
}

// ---------------- 1. zero per-dst counters + cursor ----------------
__global__ void zero_cnt_kernel(int n) {
    int i = blockIdx.x * blockDim.x + threadIdx.x;
    if (i < n) g_cnt[i] = 0;
    if (i == 0) g_total = 0;
}

// ---------------- 2. GEMM + fused attention-logit epilogue (fp32 stores) ----------------
__global__ __launch_bounds__(256) void gemm_kernel(const float* __restrict__ x,
                                                   const float* __restrict__ W,
                                                   const float* __restrict__ att_src,
                                                   const float* __restrict__ att_dst,
                                                   int n) {
    __shared__ __align__(16) float xs[32][136];
    __shared__ __align__(16) float ws[32][132];
    __shared__ float satt[2][HF];                 // [0]=att_src, [1]=att_dst
    int tid = threadIdx.x;
    int ty = tid >> 4, tx = tid & 15;
    int brow = blockIdx.x * 128;

    if (tid < 128) satt[0][tid] = att_src[tid];
    else           satt[1][tid - 128] = att_dst[tid - 128];

    u64 acc2[2][4][2][2];            // [ri][i][ci][j2]
    #pragma unroll
    for (int a = 0; a < 2; a++)
        #pragma unroll
        for (int b = 0; b < 4; b++)
            #pragma unroll
            for (int c = 0; c < 2; c++)
                #pragma unroll
                for (int d = 0; d < 2; d++) acc2[a][b][c][d] = 0ull;

    for (int kc = 0; kc < 4; kc++) {
        int k0 = kc * 32;
        #pragma unroll
        for (int it = 0; it < 4; it++) {          // x tile (transposed store)
            int f = tid + it * 256;
            int r = f >> 3, kq = f & 7;
            float4 v = make_float4(0.f, 0.f, 0.f, 0.f);
            if (brow + r < n)
                v = *(const float4*)(x + (size_t)(brow + r) * KIN + k0 + kq * 4);
            xs[kq * 4 + 0][r] = v.x; xs[kq * 4 + 1][r] = v.y;
            xs[kq * 4 + 2][r] = v.z; xs[kq * 4 + 3][r] = v.w;
        }
        #pragma unroll
        for (int it = 0; it < 4; it++) {          // W tile
            int f = tid + it * 256;
            int k = f >> 5, c4 = f & 31;
            *(float4*)&ws[k][c4 * 4] =
                *(const float4*)(W + (size_t)(k0 + k) * HF + c4 * 4);
        }
        __syncthreads();

        #pragma unroll
        for (int k = 0; k < 32; k++) {
            float4 a0 = *(float4*)&xs[k][ty * 4];
            float4 a1 = *(float4*)&xs[k][64 + ty * 4];
            float4 b0 = *(float4*)&ws[k][tx * 4];
            float4 b1 = *(float4*)&ws[k][64 + tx * 4];
            u64 bp[2][2] = {{pack2(b0.x, b0.y), pack2(b0.z, b0.w)},
                            {pack2(b1.x, b1.y), pack2(b1.z, b1.w)}};
            float av[2][4] = {{a0.x, a0.y, a0.z, a0.w}, {a1.x, a1.y, a1.z, a1.w}};
            #pragma unroll
            for (int ri = 0; ri < 2; ri++)
                #pragma unroll
                for (int i = 0; i < 4; i++) {
                    u64 ad = pack2(av[ri][i], av[ri][i]);
                    #pragma unroll
                    for (int ci = 0; ci < 2; ci++) {
                        ffma2(acc2[ri][i][ci][0], ad, bp[ci][0]);
                        ffma2(acc2[ri][i][ci][1], ad, bp[ci][1]);
                    }
                }
        }
        __syncthreads();
    }

    // epilogue: store fp32 h rows + fused a_src/a_dst
    #pragma unroll
    for (int ri = 0; ri < 2; ri++)
        #pragma unroll
        for (int i = 0; i < 4; i++) {
            int r = brow + ri * 64 + ty * 4 + i;
            float o[2][4];
            #pragma unroll
            for (int ci = 0; ci < 2; ci++) {
                unpack2(acc2[ri][i][ci][0], o[ci][0], o[ci][1]);
                unpack2(acc2[ri][i][ci][1], o[ci][2], o[ci][3]);
            }
            if (r < n) {
                #pragma unroll
                for (int ci = 0; ci < 2; ci++)
                    *(float4*)(g_h + (size_t)r * HF + ci * 64 + tx * 4) =
                        make_float4(o[ci][0], o[ci][1], o[ci][2], o[ci][3]);
            }
            float ps[2], pd[2];
            #pragma unroll
            for (int ci = 0; ci < 2; ci++) {
                const float* va = &satt[0][ci * 64 + tx * 4];
                const float* vd = &satt[1][ci * 64 + tx * 4];
                ps[ci] = o[ci][0]*va[0] + o[ci][1]*va[1] + o[ci][2]*va[2] + o[ci][3]*va[3];
                pd[ci] = o[ci][0]*vd[0] + o[ci][1]*vd[1] + o[ci][2]*vd[2] + o[ci][3]*vd[3];
            }
            #pragma unroll
            for (int off = 1; off < 8; off <<= 1) {
                #pragma unroll
                for (int ci = 0; ci < 2; ci++) {
                    ps[ci] += __shfl_xor_sync(0xffffffffu, ps[ci], off);
                    pd[ci] += __shfl_xor_sync(0xffffffffu, pd[ci], off);
                }
            }
            if ((tx & 7) == 0 && r < n) {
                int hd = tx >> 3;
                g_asrc[r * 4 + hd]     = ps[0];
                g_asrc[r * 4 + 2 + hd] = ps[1];
                g_adst[r * 4 + hd]     = pd[0];
                g_adst[r * 4 + 2 + hd] = pd[1];
            }
        }
}

// ---------------- 2b. streaming fp32 -> fp16 convert (sequential, byte-bound) ----------------
__global__ __launch_bounds__(256) void convert_kernel(size_t n8) {
    size_t i = (size_t)blockIdx.x * blockDim.x + threadIdx.x;
    if (i >= n8) return;
    const float4* src = (const float4*)g_h + i * 2;
    float4 v0 = src[0], v1 = src[1];
    __half2 h0 = __floats2half2_rn(v0.x, v0.y);
    __half2 h1 = __floats2half2_rn(v0.z, v0.w);
    __half2 h2 = __floats2half2_rn(v1.x, v1.y);
    __half2 h3 = __floats2half2_rn(v1.z, v1.w);
    uint4 u = make_uint4(*(unsigned*)&h0, *(unsigned*)&h1,
                         *(unsigned*)&h2, *(unsigned*)&h3);
    *((uint4*)g_hh + i) = u;
}

// ---------------- 3. histogram of destinations ----------------
__global__ void hist_kernel(const int* __restrict__ ei, int E) {
    int i = blockIdx.x * blockDim.x + threadIdx.x;
    if (i < E) atomicAdd(&g_cnt[ei[E + i]], 1);
}

// ---------------- 4. bucket offsets: block scan + global atomic base ----------------
__global__ __launch_bounds__(1024) void offsets_kernel(int n) {
    __shared__ int wsum[32];
    __shared__ int sbase;
    int tid = threadIdx.x, lane = tid & 31, wid = tid >> 5;
    int i = blockIdx.x * 1024 + tid;
    int v = (i < n) ? g_cnt[i] : 0;
    int incl = v;
    #pragma unroll
    for (int o = 1; o < 32; o <<= 1) {
        int t = __shfl_up_sync(0xffffffffu, incl, o);
        if (lane >= o) incl += t;
    }
    if (lane == 31) wsum[wid] = incl;
    __syncthreads();
    if (wid == 0) {
        int wv = wsum[lane];
        int wincl = wv;
        #pragma unroll
        for (int o = 1; o < 32; o <<= 1) {
            int t = __shfl_up_sync(0xffffffffu, wincl, o);
            if (lane >= o) wincl += t;
        }
        wsum[lane] = wincl - wv;
        if (lane == 31) sbase = atomicAdd(&g_total, wincl);
    }
    __syncthreads();
    int excl = incl - v + wsum[wid] + sbase;
    if (i < n) { g_off[i] = excl; g_cur[i] = excl; }
}

// ---------------- 5. bucket src indices by destination ----------------
__global__ void scatter_kernel(const int* __restrict__ ei, int E) {
    int i = blockIdx.x * blockDim.x + threadIdx.x;
    if (i >= E) return;
    int d = ei[E + i];
    int p = atomicAdd(&g_cur[d], 1);
    g_ss[p] = ei[i];
}

// ---------------- 6. single-pass gather/softmax/accumulate (warp per node) ----------------
// fp16 h gather with integer-ALU widening (no F2F pipe ops).
__global__ __launch_bounds__(256) void agg_kernel(const float* __restrict__ bias,
                                                  float* __restrict__ out, int n) {
    int w = (blockIdx.x * blockDim.x + threadIdx.x) >> 5;
    int lane = threadIdx.x & 31;
    if (w >= n) return;
    int d = w;
    int hd = lane >> 3;
    float adst = g_adst[d * 4 + hd];
    int beg = g_off[d], cnt = g_cnt[d];

    // self loop
    float e0 = g_asrc[d * 4 + hd] + adst;
    e0 = e0 > 0.f ? e0 : 0.2f * e0;
    float ex0 = __expf(e0);
    float ssum = ex0;
    float4 acc;
    {
        uint2 u = *((const uint2*)(g_hh + (size_t)d * HF) + lane);
        float2 f01 = h2f2_alu(u.x);
        float2 f23 = h2f2_alu(u.y);
        acc = make_float4(f01.x * ex0, f01.y * ex0, f23.x * ex0, f23.y * ex0);
    }

    for (int c0 = 0; c0 < cnt; c0 += 32) {
        int j = c0 + lane;
        int spre = (j < cnt) ? g_ss[beg + j] : 0;
        int m = cnt - c0; if (m > 32) m = 32;
        #pragma unroll 4
        for (int t = 0; t < m; t++) {
            int s = __shfl_sync(0xffffffffu, spre, t);
            float e = g_asrc[s * 4 + hd] + adst;
            e = e > 0.f ? e : 0.2f * e;
            float ex = __expf(e);
            ssum += ex;
            uint2 u = *((const uint2*)(g_hh + (size_t)s * HF) + lane);
            float2 f01 = h2f2_alu(u.x);
            float2 f23 = h2f2_alu(u.y);
            acc.x += f01.x * ex; acc.y += f01.y * ex;
            acc.z += f23.x * ex; acc.w += f23.y * ex;
        }
    }

    float inv = 1.0f / (ssum + 1e-16f);
    float4 b = *(const float4*)(bias + lane * 4);
    float4 o = make_float4(acc.x * inv + b.x, acc.y * inv + b.y,
                           acc.z * inv + b.z, acc.w * inv + b.w);
    *(float4*)(out + (size_t)d * HF + lane * 4) = o;
}

// ---------------- launch: fork edge-prep onto a side stream ----------------
extern "C" void kernel_launch(void* const* d_in, const int* in_sizes, int n_in,
                              void* d_out, int out_size) {
    const float* x       = (const float*)d_in[0];
    const int*   ei      = (const int*)d_in[1];     // int32 (jax default x64-disabled)
    const float* W       = (const float*)d_in[2];
    const float* att_src = (const float*)d_in[3];
    const float* att_dst = (const float*)d_in[4];
    const float* bias    = (const float*)d_in[5];
    float* out = (float*)d_out;

    int n = in_sizes[0] / KIN;     // 100000
    int E = in_sizes[1] / 2;       // 1600000

    static cudaStream_t s2 = nullptr;
    static cudaEvent_t evFork = nullptr, evJoin = nullptr;
    if (s2 == nullptr) {
        cudaStreamCreateWithFlags(&s2, cudaStreamNonBlocking);
        cudaEventCreateWithFlags(&evFork, cudaEventDisableTiming);
        cudaEventCreateWithFlags(&evJoin, cudaEventDisableTiming);
    }

    // fork: edge-prep chain on s2, GEMM chain on the launch stream
    cudaEventRecord(evFork, 0);
    cudaStreamWaitEvent(s2, evFork, 0);

    zero_cnt_kernel<<<(n + 1023) / 1024, 1024, 0, s2>>>(n);
    hist_kernel<<<(E + 255) / 256, 256, 0, s2>>>(ei, E);
    offsets_kernel<<<(n + 1023) / 1024, 1024, 0, s2>>>(n);
    scatter_kernel<<<(E + 255) / 256, 256, 0, s2>>>(ei, E);
    cudaEventRecord(evJoin, s2);

    gemm_kernel<<<(n + 127) / 128, 256>>>(x, W, att_src, att_dst, n);
    {
        size_t n8 = ((size_t)n * HF) / 8;         // 8 halves per thread
        convert_kernel<<<(unsigned)((n8 + 255) / 256), 256>>>(n8);
    }

    // join, then aggregate
    cudaStreamWaitEvent(0, evJoin, 0);
    {
        long long threads = (long long)n * 32;
        int blocks = (int)((threads + 255) / 256);
        agg_kernel<<<blocks, 256>>>(bias, out, n);
    }
}

// round 9
// speedup vs baseline: 1.3638x; 1.0508x over previous
#include <cuda_runtime.h>
#include <cuda_fp16.h>

#define NN      100000
#define EEDGES  1600000
#define KIN     128
#define HF      128      // HEADS * OUT_F
#define NHEADS  4

typedef unsigned long long u64;

// ---------------- scratch (static device globals; no allocations) ----------------
__device__ __align__(16) __half g_hh[(size_t)NN * HF];      // 25.6 MB  h = xW (fp16)
__device__ __align__(16) float g_asrc[NN * NHEADS];
__device__ __align__(16) float g_adst[NN * NHEADS];
__device__ int g_cnt[NN];          // per-dst in-degree (excl self loop)
__device__ int g_off[NN];          // bucket start per dst
__device__ int g_cur[NN];          // scatter cursors
__device__ int g_ss[EEDGES];       // src index of each edge, bucketed by dst
__device__ int g_total;            // global bucket cursor

// ---------------- f32x2 packed-FMA helpers ----------------
__device__ __forceinline__ u64 pack2(float lo, float hi) {
    u64 r; asm("mov.b64 %0, {%1, %2};" : "=l"(r) : "f"(lo), "f"(hi)); return r;
}
__device__ __forceinline__ void ffma2(u64& d, u64 a, u64 b) {
    asm("fma.rn.f32x2 %0, %1, %2, %0;" : "+l"(d) : "l"(a), "l"(b));
}
__device__ __forceinline__ void unpack2(u64 v, float& lo, float& hi) {
    asm("mov.b64 {%0, %1}, %2;" : "=f"(lo), "=f"(hi) : "l"(v));
}

// fp16x2 -> 2x fp32 via integer ALU only (no F2F pipe).
__device__ __forceinline__ float2 h2f2_alu(unsigned u) {
    unsigned lo_s = (u << 16) & 0x80000000u;
    unsigned lo_m = (u & 0x7fffu) + 0x1C000u;
    unsigned hi_s = u & 0x80000000u;
    unsigned hi_m = ((u >> 16) & 0x7fffu) + 0x1C000u;
    return make_float2(__uint_as_float(lo_s | (lo_m << 13)),
                       __uint_as_float(hi_s | (hi_m << 13)));
}

// ---------------- 1. zero per-dst counters + cursor ----------------
__global__ void zero_cnt_kernel(int n) {
    int i = blockIdx.x * blockDim.x + threadIdx.x;
    if (i < n) g_cnt[i] = 0;
    if (i == 0) g_total = 0;
}

// ---------------- 2. GEMM + fused logits, fp16 h stores ----------------
__global__ __launch_bounds__(256) void gemm_kernel(const float* __restrict__ x,
                                                   const float* __restrict__ W,
                                                   const float* __restrict__ att_src,
                                                   const float* __restrict__ att_dst,
                                                   int n) {
    __shared__ __align__(16) float xs[32][136];
    __shared__ __align__(16) float ws[32][132];
    __shared__ float satt[2][HF];                 // [0]=att_src, [1]=att_dst
    int tid = threadIdx.x;
    int ty = tid >> 4, tx = tid & 15;
    int brow = blockIdx.x * 128;

    if (tid < 128) satt[0][tid] = att_src[tid];
    else           satt[1][tid - 128] = att_dst[tid - 128];

    u64 acc2[2][4][2][2];            // [ri][i][ci][j2]
    #pragma unroll
    for (int a = 0; a < 2; a++)
        #pragma unroll
        for (int b = 0; b < 4; b++)
            #pragma unroll
            for (int c = 0; c < 2; c++)
                #pragma unroll
                for (int d = 0; d < 2; d++) acc2[a][b][c][d] = 0ull;

    for (int kc = 0; kc < 4; kc++) {
        int k0 = kc * 32;
        #pragma unroll
        for (int it = 0; it < 4; it++) {          // x tile (transposed store)
            int f = tid + it * 256;
            int r = f >> 3, kq = f & 7;
            float4 v = make_float4(0.f, 0.f, 0.f, 0.f);
            if (brow + r < n)
                v = *(const float4*)(x + (size_t)(brow + r) * KIN + k0 + kq * 4);
            xs[kq * 4 + 0][r] = v.x; xs[kq * 4 + 1][r] = v.y;
            xs[kq * 4 + 2][r] = v.z; xs[kq * 4 + 3][r] = v.w;
        }
        #pragma unroll
        for (int it = 0; it < 4; it++) {          // W tile
            int f = tid + it * 256;
            int k = f >> 5, c4 = f & 31;
            *(float4*)&ws[k][c4 * 4] =
                *(const float4*)(W + (size_t)(k0 + k) * HF + c4 * 4);
        }
        __syncthreads();

        #pragma unroll
        for (int k = 0; k < 32; k++) {
            float4 a0 = *(float4*)&xs[k][ty * 4];
            float4 a1 = *(float4*)&xs[k][64 + ty * 4];
            float4 b0 = *(float4*)&ws[k][tx * 4];
            float4 b1 = *(float4*)&ws[k][64 + tx * 4];
            u64 bp[2][2] = {{pack2(b0.x, b0.y), pack2(b0.z, b0.w)},
                            {pack2(b1.x, b1.y), pack2(b1.z, b1.w)}};
            float av[2][4] = {{a0.x, a0.y, a0.z, a0.w}, {a1.x, a1.y, a1.z, a1.w}};
            #pragma unroll
            for (int ri = 0; ri < 2; ri++)
                #pragma unroll
                for (int i = 0; i < 4; i++) {
                    u64 ad = pack2(av[ri][i], av[ri][i]);
                    #pragma unroll
                    for (int ci = 0; ci < 2; ci++) {
                        ffma2(acc2[ri][i][ci][0], ad, bp[ci][0]);
                        ffma2(acc2[ri][i][ci][1], ad, bp[ci][1]);
                    }
                }
        }
        __syncthreads();
    }

    // epilogue: fp16 h stores + fused fp32 a_src/a_dst
    #pragma unroll
    for (int ri = 0; ri < 2; ri++)
        #pragma unroll
        for (int i = 0; i < 4; i++) {
            int r = brow + ri * 64 + ty * 4 + i;
            float o[2][4];
            #pragma unroll
            for (int ci = 0; ci < 2; ci++) {
                unpack2(acc2[ri][i][ci][0], o[ci][0], o[ci][1]);
                unpack2(acc2[ri][i][ci][1], o[ci][2], o[ci][3]);
            }
            if (r < n) {
                #pragma unroll
                for (int ci = 0; ci < 2; ci++) {
                    __half2 p0 = __floats2half2_rn(o[ci][0], o[ci][1]);
                    __half2 p1 = __floats2half2_rn(o[ci][2], o[ci][3]);
                    uint2 u = make_uint2(*(unsigned*)&p0, *(unsigned*)&p1);
                    *(uint2*)(g_hh + (size_t)r * HF + ci * 64 + tx * 4) = u;
                }
            }
            float ps[2], pd[2];
            #pragma unroll
            for (int ci = 0; ci < 2; ci++) {
                const float* va = &satt[0][ci * 64 + tx * 4];
                const float* vd = &satt[1][ci * 64 + tx * 4];
                ps[ci] = o[ci][0]*va[0] + o[ci][1]*va[1] + o[ci][2]*va[2] + o[ci][3]*va[3];
                pd[ci] = o[ci][0]*vd[0] + o[ci][1]*vd[1] + o[ci][2]*vd[2] + o[ci][3]*vd[3];
            }
            #pragma unroll
            for (int off = 1; off < 8; off <<= 1) {
                #pragma unroll
                for (int ci = 0; ci < 2; ci++) {
                    ps[ci] += __shfl_xor_sync(0xffffffffu, ps[ci], off);
                    pd[ci] += __shfl_xor_sync(0xffffffffu, pd[ci], off);
                }
            }
            if ((tx & 7) == 0 && r < n) {
                int hd = tx >> 3;
                g_asrc[r * 4 + hd]     = ps[0];
                g_asrc[r * 4 + 2 + hd] = ps[1];
                g_adst[r * 4 + hd]     = pd[0];
                g_adst[r * 4 + 2 + hd] = pd[1];
            }
        }
}

// ---------------- 3. histogram of destinations ----------------
__global__ void hist_kernel(const int* __restrict__ ei, int E) {
    int i = blockIdx.x * blockDim.x + threadIdx.x;
    if (i < E) atomicAdd(&g_cnt[ei[E + i]], 1);
}

// ---------------- 4. bucket offsets: block scan + global atomic base ----------------
__global__ __launch_bounds__(1024) void offsets_kernel(int n) {
    __shared__ int wsum[32];
    __shared__ int sbase;
    int tid = threadIdx.x, lane = tid & 31, wid = tid >> 5;
    int i = blockIdx.x * 1024 + tid;
    int v = (i < n) ? g_cnt[i] : 0;
    int incl = v;
    #pragma unroll
    for (int o = 1; o < 32; o <<= 1) {
        int t = __shfl_up_sync(0xffffffffu, incl, o);
        if (lane >= o) incl += t;
    }
    if (lane == 31) wsum[wid] = incl;
    __syncthreads();
    if (wid == 0) {
        int wv = wsum[lane];
        int wincl = wv;
        #pragma unroll
        for (int o = 1; o < 32; o <<= 1) {
            int t = __shfl_up_sync(0xffffffffu, wincl, o);
            if (lane >= o) wincl += t;
        }
        wsum[lane] = wincl - wv;
        if (lane == 31) sbase = atomicAdd(&g_total, wincl);
    }
    __syncthreads();
    int excl = incl - v + wsum[wid] + sbase;
    if (i < n) { g_off[i] = excl; g_cur[i] = excl; }
}

// ---------------- 5. bucket src indices by destination ----------------
__global__ void scatter_kernel(const int* __restrict__ ei, int E) {
    int i = blockIdx.x * blockDim.x + threadIdx.x;
    if (i >= E) return;
    int d = ei[E + i];
    int p = atomicAdd(&g_cur[d], 1);
    g_ss[p] = ei[i];
}

// ---------------- 6. gather/softmax/accumulate: 2 edges per warp-iteration ----------------
// fp16 row = 256 B = 16 lanes x uint4. Low half-warp takes even edges, high half
// odd edges; per-node iterations = cnt/2. ALU widening only (no F2F).
__global__ __launch_bounds__(256) void agg_kernel(const float* __restrict__ bias,
                                                  float* __restrict__ out, int n) {
    int w = (blockIdx.x * blockDim.x + threadIdx.x) >> 5;
    int lane = threadIdx.x & 31;
    if (w >= n) return;
    int d = w;
    int ll = lane & 15;               // position within half-warp
    int hi = lane >> 4;               // half id (edge parity)
    int hd = ll >> 2;                 // head (4 lanes per head)
    float adst = g_adst[d * 4 + hd];
    int beg = g_off[d], cnt = g_cnt[d];

    float acc[8] = {0.f,0.f,0.f,0.f,0.f,0.f,0.f,0.f};
    float ssum = 0.f;

    // self loop (low half only)
    if (hi == 0) {
        float e0 = g_asrc[d * 4 + hd] + adst;
        e0 = e0 > 0.f ? e0 : 0.2f * e0;
        float ex0 = __expf(e0);
        ssum = ex0;
        uint4 u = ((const uint4*)(g_hh + (size_t)d * HF))[ll];
        float2 f;
        f = h2f2_alu(u.x); acc[0] += f.x * ex0; acc[1] += f.y * ex0;
        f = h2f2_alu(u.y); acc[2] += f.x * ex0; acc[3] += f.y * ex0;
        f = h2f2_alu(u.z); acc[4] += f.x * ex0; acc[5] += f.y * ex0;
        f = h2f2_alu(u.w); acc[6] += f.x * ex0; acc[7] += f.y * ex0;
    }

    for (int c0 = 0; c0 < cnt; c0 += 32) {
        int j = c0 + lane;
        int spre = (j < cnt) ? g_ss[beg + j] : 0;
        int m = cnt - c0; if (m > 32) m = 32;
        #pragma unroll 4
        for (int tt = 0; 2 * tt < m; tt++) {
            int idx = 2 * tt + hi;                 // edge within chunk for this half
            int s = __shfl_sync(0xffffffffu, spre, idx);
            bool valid = idx < m;
            if (!valid) s = d;                     // safe row
            float e = g_asrc[s * 4 + hd] + adst;
            e = e > 0.f ? e : 0.2f * e;
            float ex = valid ? __expf(e) : 0.f;
            ssum += ex;
            uint4 u = ((const uint4*)(g_hh + (size_t)s * HF))[ll];
            float2 f;
            f = h2f2_alu(u.x); acc[0] += f.x * ex; acc[1] += f.y * ex;
            f = h2f2_alu(u.y); acc[2] += f.x * ex; acc[3] += f.y * ex;
            f = h2f2_alu(u.z); acc[4] += f.x * ex; acc[5] += f.y * ex;
            f = h2f2_alu(u.w); acc[6] += f.x * ex; acc[7] += f.y * ex;
        }
    }

    // combine halves
    ssum += __shfl_xor_sync(0xffffffffu, ssum, 16);
    #pragma unroll
    for (int q = 0; q < 8; q++)
        acc[q] += __shfl_xor_sync(0xffffffffu, acc[q], 16);

    if (hi == 0) {
        float inv = 1.0f / (ssum + 1e-16f);
        float4 b0 = ((const float4*)bias)[ll * 2];
        float4 b1 = ((const float4*)bias)[ll * 2 + 1];
        float4 o0 = make_float4(acc[0]*inv + b0.x, acc[1]*inv + b0.y,
                                acc[2]*inv + b0.z, acc[3]*inv + b0.w);
        float4 o1 = make_float4(acc[4]*inv + b1.x, acc[5]*inv + b1.y,
                                acc[6]*inv + b1.z, acc[7]*inv + b1.w);
        float4* orow = (float4*)(out + (size_t)d * HF);
        orow[ll * 2]     = o0;
        orow[ll * 2 + 1] = o1;
    }
}

// ---------------- launch: fork edge-prep onto a side stream ----------------
extern "C" void kernel_launch(void* const* d_in, const int* in_sizes, int n_in,
                              void* d_out, int out_size) {
    const float* x       = (const float*)d_in[0];
    const int*   ei      = (const int*)d_in[1];     // int32 (jax default x64-disabled)
    const float* W       = (const float*)d_in[2];
    const float* att_src = (const float*)d_in[3];
    const float* att_dst = (const float*)d_in[4];
    const float* bias    = (const float*)d_in[5];
    float* out = (float*)d_out;

    int n = in_sizes[0] / KIN;     // 100000
    int E = in_sizes[1] / 2;       // 1600000

    static cudaStream_t s2 = nullptr;
    static cudaEvent_t evFork = nullptr, evJoin = nullptr;
    if (s2 == nullptr) {
        cudaStreamCreateWithFlags(&s2, cudaStreamNonBlocking);
        cudaEventCreateWithFlags(&evFork, cudaEventDisableTiming);
        cudaEventCreateWithFlags(&evJoin, cudaEventDisableTiming);
    }

    // fork: edge-prep chain on s2, GEMM chain on the launch stream
    cudaEventRecord(evFork, 0);
    cudaStreamWaitEvent(s2, evFork, 0);

    zero_cnt_kernel<<<(n + 1023) / 1024, 1024, 0, s2>>>(n);
    hist_kernel<<<(E + 255) / 256, 256, 0, s2>>>(ei, E);
    offsets_kernel<<<(n + 1023) / 1024, 1024, 0, s2>>>(n);
    scatter_kernel<<<(E + 255) / 256, 256, 0, s2>>>(ei, E);
    cudaEventRecord(evJoin, s2);

    gemm_kernel<<<(n + 127) / 128, 256>>>(x, W, att_src, att_dst, n);

    // join, then aggregate
    cudaStreamWaitEvent(0, evJoin, 0);
    {
        long long threads = (long long)n * 32;
        int blocks = (int)((threads + 255) / 256);
        agg_kernel<<<blocks, 256>>>(bias, out, n);
    }
}